// round 1
// baseline (speedup 1.0000x reference)
#include <cuda_runtime.h>
#include <math.h>

// ---------------- problem constants ----------------
#define EDIM   768
#define NTOK   197
#define BSZ    16
#define ROWS   (BSZ*NTOK)      // 3152
#define MFEAT  256
#define FDIM   3072
#define NPATCH 196
#define NC     1000
#define NLAYER 12

#define SCAL  0.18995897f      // 768^{-1/4}
#define MSCL  0.0625f          // 256^{-1/2}
#define FEPS  1e-4f

// ---------------- scratch (device globals; allocation-free) ----------------
__device__ float g_h   [ROWS*EDIM];        // residual stream
__device__ float g_y   [ROWS*EDIM];        // LN output
__device__ float g_tmp [ROWS*FDIM];        // MLP hidden; also im2col + tok at start
__device__ float g_lg  [ROWS*MFEAT];       // logits -> lg
__device__ float g_qf  [ROWS*MFEAT];
__device__ float g_kf  [ROWS*MFEAT];
__device__ float g_kv  [BSZ*MFEAT*EDIM];
__device__ float g_diag[ROWS];
__device__ float g_qmax[ROWS];
__device__ float g_den [ROWS];
__device__ float g_ksum[BSZ*MFEAT];
__device__ float g_gmax[1];
__device__ float g_cls [BSZ*EDIM];

// ---------------- generic tiled SGEMM ----------------
// C[M,N] = op(A) @ op(B); ld of C is always N.
// !TA: A[M,K], TA: A[K,M]; !TB: B[K,N], TB: B[N,K].
// flags: 1=+bias[n]  2=gelu  4=accumulate into C  8=divide by rowdiv[z*M+m]
template<bool TA, bool TB>
__global__ void __launch_bounds__(256) gemm_kernel(
    const float* __restrict__ A, const float* __restrict__ B, float* __restrict__ C,
    int M, int N, int K,
    long long sA, long long sB, long long sC,
    const float* __restrict__ bias, const float* __restrict__ rowdiv, int flags)
{
    __shared__ __align__(16) float As[8][128];
    __shared__ __align__(16) float Bs[8][128];
    int tid = threadIdx.x;
    int m0 = blockIdx.y * 128;
    int n0 = blockIdx.x * 128;
    int z  = blockIdx.z;
    A += (long long)z * sA;
    B += (long long)z * sB;
    C += (long long)z * sC;

    int tx = tid & 15;
    int ty = tid >> 4;

    float acc[8][8];
#pragma unroll
    for (int i = 0; i < 8; i++)
#pragma unroll
        for (int j = 0; j < 8; j++) acc[i][j] = 0.f;

    for (int k0 = 0; k0 < K; k0 += 8) {
#pragma unroll
        for (int i = 0; i < 4; i++) {
            int l = tid + i * 256;
            if (TA) {
                int k = l >> 7, m = l & 127;
                int gk = k0 + k, gm = m0 + m;
                As[k][m] = (gk < K && gm < M) ? A[(long long)gk * M + gm] : 0.f;
            } else {
                int m = l >> 3, k = l & 7;
                int gk = k0 + k, gm = m0 + m;
                As[k][m] = (gk < K && gm < M) ? A[(long long)gm * K + gk] : 0.f;
            }
        }
#pragma unroll
        for (int i = 0; i < 4; i++) {
            int l = tid + i * 256;
            if (TB) {
                int n = l >> 3, k = l & 7;
                int gk = k0 + k, gn = n0 + n;
                Bs[k][n] = (gk < K && gn < N) ? B[(long long)gn * K + gk] : 0.f;
            } else {
                int k = l >> 7, n = l & 127;
                int gk = k0 + k, gn = n0 + n;
                Bs[k][n] = (gk < K && gn < N) ? B[(long long)gk * N + gn] : 0.f;
            }
        }
        __syncthreads();
#pragma unroll
        for (int k = 0; k < 8; k++) {
            float4 a0 = *(const float4*)&As[k][ty * 4];
            float4 a1 = *(const float4*)&As[k][ty * 4 + 64];
            float4 b0 = *(const float4*)&Bs[k][tx * 4];
            float4 b1 = *(const float4*)&Bs[k][tx * 4 + 64];
            float af[8] = {a0.x, a0.y, a0.z, a0.w, a1.x, a1.y, a1.z, a1.w};
            float bf[8] = {b0.x, b0.y, b0.z, b0.w, b1.x, b1.y, b1.z, b1.w};
#pragma unroll
            for (int i = 0; i < 8; i++)
#pragma unroll
                for (int j = 0; j < 8; j++) acc[i][j] += af[i] * bf[j];
        }
        __syncthreads();
    }

#pragma unroll
    for (int i = 0; i < 8; i++) {
        int gm = m0 + ((i < 4) ? ty * 4 + i : 64 + ty * 4 + (i - 4));
        if (gm >= M) continue;
        float dv = 1.0f;
        if (flags & 8) dv = 1.0f / rowdiv[(long long)z * M + gm];
        float* crow = C + (long long)gm * N;
#pragma unroll
        for (int j = 0; j < 8; j++) {
            int gn = n0 + ((j < 4) ? tx * 4 + j : 64 + tx * 4 + (j - 4));
            if (gn >= N) continue;
            float v = acc[i][j];
            if (flags & 1) v += bias[gn];
            if (flags & 2) v = 0.5f * v * (1.0f + erff(v * 0.70710678118654752f));
            if (flags & 8) v *= dv;
            if (flags & 4) v += crow[gn];
            crow[gn] = v;
        }
    }
}

// ---------------- layernorm (row = block of 256 threads, 768 cols) ----------------
__global__ void ln_kernel(const float* __restrict__ X, long long ldx,
                          float* __restrict__ Y, long long ldy,
                          const float* __restrict__ g, const float* __restrict__ b,
                          float* __restrict__ diag)
{
    int row = blockIdx.x;
    const float* x = X + (long long)row * ldx;
    float* y = Y + (long long)row * ldy;
    int tid = threadIdx.x;
    float v0 = x[tid], v1 = x[tid + 256], v2 = x[tid + 512];
    float s1 = v0 + v1 + v2;
    float s2 = v0 * v0 + v1 * v1 + v2 * v2;
    __shared__ float red[64];
#pragma unroll
    for (int o = 16; o > 0; o >>= 1) {
        s1 += __shfl_down_sync(0xffffffffu, s1, o);
        s2 += __shfl_down_sync(0xffffffffu, s2, o);
    }
    int w = tid >> 5, lane = tid & 31;
    if (lane == 0) { red[w] = s1; red[w + 8] = s2; }
    __syncthreads();
    if (tid == 0) {
        float a = 0.f, c = 0.f;
        for (int i = 0; i < 8; i++) { a += red[i]; c += red[i + 8]; }
        red[16] = a; red[17] = c;
    }
    __syncthreads();
    float mu  = red[16] * (1.0f / 768.0f);
    float var = red[17] * (1.0f / 768.0f) - mu * mu;
    float inv = rsqrtf(var + 1e-5f);
    float y0 = (v0 - mu) * inv * g[tid]       + b[tid];
    float y1 = (v1 - mu) * inv * g[tid + 256] + b[tid + 256];
    float y2 = (v2 - mu) * inv * g[tid + 512] + b[tid + 512];
    y[tid] = y0; y[tid + 256] = y1; y[tid + 512] = y2;
    if (diag) {
        float d = y0 * y0 + y1 * y1 + y2 * y2;
#pragma unroll
        for (int o = 16; o > 0; o >>= 1) d += __shfl_down_sync(0xffffffffu, d, o);
        if (lane == 0) red[32 + w] = d;
        __syncthreads();
        if (tid == 0) {
            float a = 0.f;
            for (int i = 0; i < 8; i++) a += red[32 + i];
            diag[row] = 0.5f * SCAL * SCAL * a;
        }
    }
}

// ---------------- performer helper kernels ----------------
// lg = raw*SCAL - diag[row]  (in place), qmax[row] = max_m lg
__global__ void lg_rowmax_kernel(float* __restrict__ lg, const float* __restrict__ diag,
                                 float* __restrict__ qmax)
{
    int row = blockIdx.x;
    int tid = threadIdx.x;                // 256 threads, MFEAT=256
    long long idx = (long long)row * MFEAT + tid;
    float v = lg[idx] * SCAL - diag[row];
    lg[idx] = v;
    __shared__ float red[8];
    float m = v;
#pragma unroll
    for (int o = 16; o > 0; o >>= 1) m = fmaxf(m, __shfl_down_sync(0xffffffffu, m, o));
    int w = tid >> 5, lane = tid & 31;
    if (lane == 0) red[w] = m;
    __syncthreads();
    if (tid == 0) {
        float a = red[0];
        for (int i = 1; i < 8; i++) a = fmaxf(a, red[i]);
        qmax[row] = a;
    }
}

__global__ void gmax_kernel(const float* __restrict__ qmax, float* __restrict__ gmax)
{
    int tid = threadIdx.x;
    float m = -1e30f;
    for (int i = tid; i < ROWS; i += 256) m = fmaxf(m, qmax[i]);
    __shared__ float red[8];
#pragma unroll
    for (int o = 16; o > 0; o >>= 1) m = fmaxf(m, __shfl_down_sync(0xffffffffu, m, o));
    int w = tid >> 5, lane = tid & 31;
    if (lane == 0) red[w] = m;
    __syncthreads();
    if (tid == 0) {
        float a = red[0];
        for (int i = 1; i < 8; i++) a = fmaxf(a, red[i]);
        gmax[0] = a;
    }
}

__global__ void feat_kernel(const float* __restrict__ lg, const float* __restrict__ qmax,
                            const float* __restrict__ gmax,
                            float* __restrict__ qf, float* __restrict__ kf)
{
    long long i = (long long)blockIdx.x * 256 + threadIdx.x;
    if (i >= (long long)ROWS * MFEAT) return;
    int row = (int)(i >> 8);
    float v = lg[i];
    float gm = gmax[0];
    qf[i] = expf(v - qmax[row]) * MSCL + FEPS;
    kf[i] = expf(v - gm)        * MSCL + FEPS;
}

__global__ void ksum_kernel(const float* __restrict__ kf, float* __restrict__ ksum)
{
    int b = blockIdx.x;        // 16 blocks
    int m = threadIdx.x;       // 256 threads
    float s = 0.f;
    const float* base = kf + (long long)b * NTOK * MFEAT + m;
    for (int n = 0; n < NTOK; n++) s += base[(long long)n * MFEAT];
    ksum[b * MFEAT + m] = s;
}

__global__ void den_kernel(const float* __restrict__ qf, const float* __restrict__ ksum,
                           float* __restrict__ den)
{
    int warp = (blockIdx.x * blockDim.x + threadIdx.x) >> 5;
    int lane = threadIdx.x & 31;
    if (warp >= ROWS) return;
    int b = warp / NTOK;
    const float* q  = qf   + (long long)warp * MFEAT;
    const float* ks = ksum + b * MFEAT;
    float s = 0.f;
#pragma unroll
    for (int m = lane; m < MFEAT; m += 32) s += q[m] * ks[m];
#pragma unroll
    for (int o = 16; o > 0; o >>= 1) s += __shfl_down_sync(0xffffffffu, s, o);
    if (lane == 0) den[warp] = s;
}

// ---------------- patch embed ----------------
__global__ void im2col_kernel(const float* __restrict__ x, float* __restrict__ pt)
{
    long long i = (long long)blockIdx.x * 256 + threadIdx.x;
    if (i >= (long long)BSZ * NPATCH * 768) return;
    int kidx = (int)(i % 768);
    int p    = (int)(i / 768);
    int pj = kidx & 15, pi = (kidx >> 4) & 15, c = kidx >> 8;
    int gj = p % 14;
    int t  = p / 14;
    int gi = t % 14;
    int b  = t / 14;
    pt[i] = x[(((long long)(b * 3 + c) * 224 + gi * 16 + pi) * 224) + gj * 16 + pj];
}

__global__ void assemble_kernel(const float* __restrict__ tok, const float* __restrict__ cls_tok,
                                const float* __restrict__ pos, float* __restrict__ h)
{
    long long i = (long long)blockIdx.x * 256 + threadIdx.x;
    if (i >= (long long)ROWS * EDIM) return;
    int e = (int)(i % EDIM);
    int t = (int)(i / EDIM);
    int n = t % NTOK;
    int b = t / NTOK;
    float v = (n == 0) ? cls_tok[e] : tok[(long long)(b * NPATCH + n - 1) * EDIM + e];
    h[i] = v + pos[(long long)n * EDIM + e];
}

// ---------------- host driver ----------------
static inline float* sym(const void* s)
{
    void* p = nullptr;
    cudaGetSymbolAddress(&p, s);
    return (float*)p;
}

extern "C" void kernel_launch(void* const* d_in, const int* in_sizes, int n_in,
                              void* d_out, int out_size)
{
    const float* x       = (const float*)d_in[0];
    const float* cls_tok = (const float*)d_in[1];
    const float* pos_emb = (const float*)d_in[2];
    const float* patch_w = (const float*)d_in[3];
    const float* patch_b = (const float*)d_in[4];
    const float* ln1_g   = (const float*)d_in[5];
    const float* ln1_b   = (const float*)d_in[6];
    const float* proj    = (const float*)d_in[7];
    const float* ln2_g   = (const float*)d_in[8];
    const float* ln2_b   = (const float*)d_in[9];
    const float* w1      = (const float*)d_in[10];
    const float* b1      = (const float*)d_in[11];
    const float* w2      = (const float*)d_in[12];
    const float* b2      = (const float*)d_in[13];
    const float* lnf_g   = (const float*)d_in[14];
    const float* lnf_b   = (const float*)d_in[15];
    const float* head_w  = (const float*)d_in[16];
    const float* head_b  = (const float*)d_in[17];
    float* out = (float*)d_out;

    float* h    = sym(g_h);
    float* y    = sym(g_y);
    float* tmp  = sym(g_tmp);
    float* lg   = sym(g_lg);
    float* qf   = sym(g_qf);
    float* kf   = sym(g_kf);
    float* kv   = sym(g_kv);
    float* diag = sym(g_diag);
    float* qmax = sym(g_qmax);
    float* den  = sym(g_den);
    float* ksum = sym(g_ksum);
    float* gmax = sym(g_gmax);
    float* clsb = sym(g_cls);

    float* pt  = tmp;             // [3136,768] im2col
    float* tok = tmp + 5000000;   // [3136,768] patch-embed out

    // --- patch embedding ---
    {
        long long tot = (long long)BSZ * NPATCH * 768;
        im2col_kernel<<<(unsigned)((tot + 255) / 256), 256>>>(x, pt);
        dim3 grid(6, 25, 1); // N=768, M=3136
        gemm_kernel<false, true><<<grid, 256>>>(pt, patch_w, tok,
            BSZ * NPATCH, EDIM, 768, 0, 0, 0, patch_b, nullptr, 1);
        long long ht = (long long)ROWS * EDIM;
        assemble_kernel<<<(unsigned)((ht + 255) / 256), 256>>>(tok, cls_tok, pos_emb, h);
    }

    for (int l = 0; l < NLAYER; l++) {
        const float* prj = proj + (long long)l * MFEAT * EDIM;
        // LN1 + diag
        ln_kernel<<<ROWS, 256>>>(h, EDIM, y, EDIM, ln1_g + l * EDIM, ln1_b + l * EDIM, diag);
        // logits = y @ proj^T  (raw)
        {
            dim3 grid(2, 25, 1); // N=256, M=3152
            gemm_kernel<false, true><<<grid, 256>>>(y, prj, lg,
                ROWS, MFEAT, EDIM, 0, 0, 0, nullptr, nullptr, 0);
        }
        lg_rowmax_kernel<<<ROWS, 256>>>(lg, diag, qmax);
        gmax_kernel<<<1, 256>>>(qmax, gmax);
        feat_kernel<<<(ROWS * MFEAT + 255) / 256, 256>>>(lg, qmax, gmax, qf, kf);
        ksum_kernel<<<BSZ, 256>>>(kf, ksum);
        // kv[b] = kf[b]^T @ y[b]  : [256,768], K=197
        {
            dim3 grid(6, 2, BSZ);
            gemm_kernel<true, false><<<grid, 256>>>(kf, y, kv,
                MFEAT, EDIM, NTOK,
                (long long)NTOK * MFEAT, (long long)NTOK * EDIM, (long long)MFEAT * EDIM,
                nullptr, nullptr, 0);
        }
        den_kernel<<<(ROWS + 7) / 8, 256>>>(qf, ksum, den);
        // h += (qf @ kv) / den
        {
            dim3 grid(6, 2, BSZ);
            gemm_kernel<false, false><<<grid, 256>>>(qf, kv, h,
                NTOK, EDIM, MFEAT,
                (long long)NTOK * MFEAT, (long long)MFEAT * EDIM, (long long)NTOK * EDIM,
                nullptr, den, 4 | 8);
        }
        // LN2
        ln_kernel<<<ROWS, 256>>>(h, EDIM, y, EDIM, ln2_g + l * EDIM, ln2_b + l * EDIM, nullptr);
        // hid = gelu(y @ w1 + b1)
        {
            dim3 grid(24, 25, 1);
            gemm_kernel<false, false><<<grid, 256>>>(y, w1 + (long long)l * EDIM * FDIM, tmp,
                ROWS, FDIM, EDIM, 0, 0, 0, b1 + l * FDIM, nullptr, 1 | 2);
        }
        // h += hid @ w2 + b2
        {
            dim3 grid(6, 25, 1);
            gemm_kernel<false, false><<<grid, 256>>>(tmp, w2 + (long long)l * FDIM * EDIM, h,
                ROWS, EDIM, FDIM, 0, 0, 0, b2 + l * EDIM, nullptr, 1 | 4);
        }
    }

    // final LN on CLS tokens + head
    ln_kernel<<<BSZ, 256>>>(h, (long long)NTOK * EDIM, clsb, EDIM, lnf_g, lnf_b, nullptr);
    {
        dim3 grid(8, 1, 1); // N=1000, M=16
        gemm_kernel<false, false><<<grid, 256>>>(clsb, head_w, out,
            BSZ, NC, EDIM, 0, 0, 0, head_b, nullptr, 1);
    }
}

// round 6
// speedup vs baseline: 2.3867x; 2.3867x over previous
#include <cuda_runtime.h>
#include <cuda_bf16.h>
#include <math.h>
#include <stdint.h>

// ---------------- problem constants ----------------
#define EDIM   768
#define NTOK   197
#define BSZ    16
#define ROWS   (BSZ*NTOK)      // 3152
#define MFEAT  256
#define FDIM   3072
#define NPATCH 196
#define NC     1000
#define NLAYER 12
#define KPAD   224             // 197 padded to mult of 32

#define SCAL  0.18995897f      // 768^{-1/4}
#define MSCL  0.0625f          // 256^{-1/2}
#define FEPS  1e-4f

// ---------------- scratch (device globals; allocation-free) ----------------
__device__ float g_h   [ROWS*EDIM];
__device__ float g_y   [ROWS*EDIM];
__device__ float g_tmp [ROWS*FDIM];          // MLP hidden; im2col+tok at start
__device__ float g_lg  [ROWS*MFEAT];
__device__ float g_qf  [ROWS*MFEAT];
__device__ float g_kfT [BSZ*MFEAT*KPAD];     // [b][m][t] zero-padded t>=197
__device__ float g_yT  [BSZ*EDIM*KPAD];      // [b][e][t] zero-padded
__device__ float g_kvT [BSZ*EDIM*MFEAT];     // [b][e][m]
__device__ float g_part[2*ROWS*EDIM];        // split-K partials
__device__ float g_diag[ROWS];
__device__ float g_qmax[ROWS];
__device__ float g_den [ROWS];
__device__ float g_ksum[BSZ*MFEAT];
__device__ float g_gmax[1];
__device__ float g_cls [BSZ*EDIM];
__device__ float g_w1T [NLAYER*EDIM*FDIM];   // [l][f][e]
__device__ float g_w2T [NLAYER*EDIM*FDIM];   // [l][e][f]

// ================= bf16-split mma.sync GEMM =================
// C[M, N=grid.x*128] = A[M,klen] @ B[N,klen]^T   (both fp32 K-major)
// 2-term bf16 split, 3 products: fp32-like accuracy (~3e-5 per product).
// flags: 1=+bias[n]  2=gelu  4=accumulate into C  8=divide by rowdiv[z*sdiv+m]

#define SPITCH 40   // smem row pitch in halfs (80 bytes = 20 words: conflict-free)

__device__ __forceinline__ void mma_bf16(float* c, const uint32_t* a, const uint32_t* b)
{
    asm volatile(
        "mma.sync.aligned.m16n8k16.row.col.f32.bf16.bf16.f32 "
        "{%0,%1,%2,%3}, {%4,%5,%6,%7}, {%8,%9}, {%0,%1,%2,%3};"
        : "+f"(c[0]), "+f"(c[1]), "+f"(c[2]), "+f"(c[3])
        : "r"(a[0]), "r"(a[1]), "r"(a[2]), "r"(a[3]), "r"(b[0]), "r"(b[1]));
}

__device__ __forceinline__ uint32_t ld_half2(const __nv_bfloat16* p)
{
    return *(const uint32_t*)p;
}

// split float4 -> packed hi(2xuint) and lo(2xuint) bf16x2
__device__ __forceinline__ void split_pack(float4 v, uint2& hi, uint2& lo)
{
    __nv_bfloat16 hx = __float2bfloat16(v.x);
    __nv_bfloat16 hy = __float2bfloat16(v.y);
    __nv_bfloat16 hz = __float2bfloat16(v.z);
    __nv_bfloat16 hw = __float2bfloat16(v.w);
    __nv_bfloat16 lx = __float2bfloat16(v.x - __bfloat162float(hx));
    __nv_bfloat16 ly = __float2bfloat16(v.y - __bfloat162float(hy));
    __nv_bfloat16 lz = __float2bfloat16(v.z - __bfloat162float(hz));
    __nv_bfloat16 lw = __float2bfloat16(v.w - __bfloat162float(hw));
    __nv_bfloat162 h0 = __halves2bfloat162(hx, hy);
    __nv_bfloat162 h1 = __halves2bfloat162(hz, hw);
    __nv_bfloat162 l0 = __halves2bfloat162(lx, ly);
    __nv_bfloat162 l1 = __halves2bfloat162(lz, lw);
    hi.x = *(uint32_t*)&h0; hi.y = *(uint32_t*)&h1;
    lo.x = *(uint32_t*)&l0; lo.y = *(uint32_t*)&l1;
}

__global__ void __launch_bounds__(256) mma_gemm(
    const float* __restrict__ A, const float* __restrict__ B, float* __restrict__ C,
    int M, int ldA, int ldB, int ldC,
    long long sA, long long sB, long long sC,
    int kstart, int kzs, int klen,
    const float* __restrict__ bias, const float* __restrict__ rowdiv, int sdiv, int flags)
{
    __shared__ __align__(16) __nv_bfloat16 Ah[128 * SPITCH];
    __shared__ __align__(16) __nv_bfloat16 Al[128 * SPITCH];
    __shared__ __align__(16) __nv_bfloat16 Bh[128 * SPITCH];
    __shared__ __align__(16) __nv_bfloat16 Bl[128 * SPITCH];

    int tid = threadIdx.x;
    int wid = tid >> 5, lane = tid & 31;
    int m0 = blockIdx.y * 128, n0 = blockIdx.x * 128, z = blockIdx.z;
    int warpM = wid >> 2;          // 0..1 -> 64 rows
    int warpN = wid & 3;           // 0..3 -> 32 cols
    int qr = lane >> 2;            // group row 0..7
    int qc = (lane & 3) * 2;       // k pair base

    const float* Ab = A + (long long)z * sA + kstart + (long long)z * kzs;
    const float* Bb = B + (long long)z * sB + kstart + (long long)z * kzs;

    float acc[4][4][4];
#pragma unroll
    for (int i = 0; i < 4; i++)
#pragma unroll
        for (int j = 0; j < 4; j++)
#pragma unroll
            for (int r = 0; r < 4; r++) acc[i][j][r] = 0.f;

    int kt_n = klen >> 5;

    // prefetch tile 0 into regs
    float4 av[4], bv[4];
#pragma unroll
    for (int i = 0; i < 4; i++) {
        int idx = tid + (i << 8);
        int r = idx >> 3, c4 = idx & 7;
        int gm = m0 + r;
        av[i] = (gm < M) ? *(const float4*)(Ab + (long long)gm * ldA + (c4 << 2))
                         : make_float4(0.f, 0.f, 0.f, 0.f);
        bv[i] = *(const float4*)(Bb + (long long)(n0 + r) * ldB + (c4 << 2));
    }

    for (int kt = 0; kt < kt_n; kt++) {
        __syncthreads();   // previous compute done; smem reusable
        // convert + store current tile
#pragma unroll
        for (int i = 0; i < 4; i++) {
            int idx = tid + (i << 8);
            int r = idx >> 3, c4 = idx & 7;
            int ho = r * SPITCH + c4 * 4;
            uint2 hi, lo;
            split_pack(av[i], hi, lo);
            *(uint2*)&Ah[ho] = hi; *(uint2*)&Al[ho] = lo;
            split_pack(bv[i], hi, lo);
            *(uint2*)&Bh[ho] = hi; *(uint2*)&Bl[ho] = lo;
        }
        __syncthreads();
        // prefetch next tile
        if (kt + 1 < kt_n) {
            long long ko = ((long long)(kt + 1) << 5);
#pragma unroll
            for (int i = 0; i < 4; i++) {
                int idx = tid + (i << 8);
                int r = idx >> 3, c4 = idx & 7;
                int gm = m0 + r;
                av[i] = (gm < M) ? *(const float4*)(Ab + (long long)gm * ldA + ko + (c4 << 2))
                                 : make_float4(0.f, 0.f, 0.f, 0.f);
                bv[i] = *(const float4*)(Bb + (long long)(n0 + r) * ldB + ko + (c4 << 2));
            }
        }
        // compute 32-deep K slab
#pragma unroll
        for (int ks = 0; ks < 2; ks++) {
            int kb = ks * 16 + qc;
            uint32_t bhf[4][2], blf[4][2];
#pragma unroll
            for (int nt = 0; nt < 4; nt++) {
                int nb = warpN * 32 + nt * 8 + qr;
                bhf[nt][0] = ld_half2(&Bh[nb * SPITCH + kb]);
                bhf[nt][1] = ld_half2(&Bh[nb * SPITCH + kb + 8]);
                blf[nt][0] = ld_half2(&Bl[nb * SPITCH + kb]);
                blf[nt][1] = ld_half2(&Bl[nb * SPITCH + kb + 8]);
            }
#pragma unroll
            for (int mt = 0; mt < 4; mt++) {
                int mb = warpM * 64 + mt * 16 + qr;
                uint32_t ahf[4], alf[4];
                ahf[0] = ld_half2(&Ah[mb * SPITCH + kb]);
                ahf[1] = ld_half2(&Ah[(mb + 8) * SPITCH + kb]);
                ahf[2] = ld_half2(&Ah[mb * SPITCH + kb + 8]);
                ahf[3] = ld_half2(&Ah[(mb + 8) * SPITCH + kb + 8]);
                alf[0] = ld_half2(&Al[mb * SPITCH + kb]);
                alf[1] = ld_half2(&Al[(mb + 8) * SPITCH + kb]);
                alf[2] = ld_half2(&Al[mb * SPITCH + kb + 8]);
                alf[3] = ld_half2(&Al[(mb + 8) * SPITCH + kb + 8]);
#pragma unroll
                for (int nt = 0; nt < 4; nt++) {
                    mma_bf16(acc[mt][nt], ahf, bhf[nt]);
                    mma_bf16(acc[mt][nt], ahf, blf[nt]);
                    mma_bf16(acc[mt][nt], alf, bhf[nt]);
                }
            }
        }
    }

    // ---- epilogue ----
#pragma unroll
    for (int mt = 0; mt < 4; mt++) {
        int r0 = m0 + warpM * 64 + mt * 16 + qr;
        int r1 = r0 + 8;
        bool ok0 = r0 < M, ok1 = r1 < M;
        float dv0 = 1.f, dv1 = 1.f;
        if (flags & 8) {
            if (ok0) dv0 = 1.f / rowdiv[(long long)z * sdiv + r0];
            if (ok1) dv1 = 1.f / rowdiv[(long long)z * sdiv + r1];
        }
        float* row0 = C + (long long)z * sC + (long long)r0 * ldC;
        float* row1 = C + (long long)z * sC + (long long)r1 * ldC;
#pragma unroll
        for (int nt = 0; nt < 4; nt++) {
            int col = n0 + warpN * 32 + nt * 8 + qc;
            float b0 = 0.f, b1 = 0.f;
            if (flags & 1) { b0 = bias[col]; b1 = bias[col + 1]; }
#pragma unroll
            for (int half = 0; half < 2; half++) {
                bool ok = half ? ok1 : ok0;
                if (!ok) continue;
                float dv = half ? dv1 : dv0;
                float* row = half ? row1 : row0;
                float v0 = acc[mt][nt][half * 2 + 0];
                float v1 = acc[mt][nt][half * 2 + 1];
                v0 += b0; v1 += b1;
                if (flags & 2) {
                    v0 = 0.5f * v0 * (1.f + erff(v0 * 0.70710678118654752f));
                    v1 = 0.5f * v1 * (1.f + erff(v1 * 0.70710678118654752f));
                }
                if (flags & 8) { v0 *= dv; v1 *= dv; }
                if (flags & 4) { v0 += row[col]; v1 += row[col + 1]; }
                row[col] = v0; row[col + 1] = v1;
            }
        }
    }
}

// ================= fallback SGEMM (head only) =================
__global__ void __launch_bounds__(256) gemm_kernel(
    const float* __restrict__ A, const float* __restrict__ B, float* __restrict__ C,
    int M, int N, int K,
    const float* __restrict__ bias, int flags)
{
    __shared__ __align__(16) float As[8][128];
    __shared__ __align__(16) float Bs[8][128];
    int tid = threadIdx.x;
    int m0 = blockIdx.y * 128;
    int n0 = blockIdx.x * 128;
    int tx = tid & 15, ty = tid >> 4;
    float acc[8][8];
#pragma unroll
    for (int i = 0; i < 8; i++)
#pragma unroll
        for (int j = 0; j < 8; j++) acc[i][j] = 0.f;
    for (int k0 = 0; k0 < K; k0 += 8) {
#pragma unroll
        for (int i = 0; i < 4; i++) {
            int l = tid + i * 256;
            int mm = l >> 3, kk = l & 7;
            int gk = k0 + kk, gm = m0 + mm;
            As[kk][mm] = (gk < K && gm < M) ? A[(long long)gm * K + gk] : 0.f;
        }
#pragma unroll
        for (int i = 0; i < 4; i++) {
            int l = tid + i * 256;
            int kk = l >> 7, nn = l & 127;
            int gk = k0 + kk, gn = n0 + nn;
            Bs[kk][nn] = (gk < K && gn < N) ? B[(long long)gk * N + gn] : 0.f;
        }
        __syncthreads();
#pragma unroll
        for (int k = 0; k < 8; k++) {
            float4 a0 = *(const float4*)&As[k][ty * 4];
            float4 a1 = *(const float4*)&As[k][ty * 4 + 64];
            float4 b0 = *(const float4*)&Bs[k][tx * 4];
            float4 b1 = *(const float4*)&Bs[k][tx * 4 + 64];
            float af[8] = {a0.x, a0.y, a0.z, a0.w, a1.x, a1.y, a1.z, a1.w};
            float bf[8] = {b0.x, b0.y, b0.z, b0.w, b1.x, b1.y, b1.z, b1.w};
#pragma unroll
            for (int i = 0; i < 8; i++)
#pragma unroll
                for (int j = 0; j < 8; j++) acc[i][j] += af[i] * bf[j];
        }
        __syncthreads();
    }
#pragma unroll
    for (int i = 0; i < 8; i++) {
        int gm = m0 + ((i < 4) ? ty * 4 + i : 64 + ty * 4 + (i - 4));
        if (gm >= M) continue;
        float* crow = C + (long long)gm * N;
#pragma unroll
        for (int j = 0; j < 8; j++) {
            int gn = n0 + ((j < 4) ? tx * 4 + j : 64 + tx * 4 + (j - 4));
            if (gn >= N) continue;
            float v = acc[i][j];
            if (flags & 1) v += bias[gn];
            crow[gn] = v;
        }
    }
}

// ================= layernorm: warp per row =================
__global__ void ln_kernel(const float* __restrict__ X, long long ldx,
                          float* __restrict__ Y, long long ldy,
                          const float* __restrict__ g, const float* __restrict__ b,
                          float* __restrict__ diag, int nrows)
{
    int w = blockIdx.x * (blockDim.x >> 5) + (threadIdx.x >> 5);
    int lane = threadIdx.x & 31;
    if (w >= nrows) return;
    const float4* x = (const float4*)(X + (long long)w * ldx);
    float4 v[6];
    float s1 = 0.f, s2 = 0.f;
#pragma unroll
    for (int i = 0; i < 6; i++) {
        v[i] = x[lane + 32 * i];
        s1 += v[i].x + v[i].y + v[i].z + v[i].w;
        s2 += v[i].x * v[i].x + v[i].y * v[i].y + v[i].z * v[i].z + v[i].w * v[i].w;
    }
#pragma unroll
    for (int o = 16; o > 0; o >>= 1) {
        s1 += __shfl_xor_sync(0xffffffffu, s1, o);
        s2 += __shfl_xor_sync(0xffffffffu, s2, o);
    }
    float mu  = s1 * (1.0f / 768.0f);
    float var = s2 * (1.0f / 768.0f) - mu * mu;
    float inv = rsqrtf(var + 1e-5f);
    const float4* g4 = (const float4*)g;
    const float4* b4 = (const float4*)b;
    float4* y4 = (float4*)(Y + (long long)w * ldy);
    float d = 0.f;
#pragma unroll
    for (int i = 0; i < 6; i++) {
        float4 gv = g4[lane + 32 * i], bv = b4[lane + 32 * i], o;
        o.x = (v[i].x - mu) * inv * gv.x + bv.x;
        o.y = (v[i].y - mu) * inv * gv.y + bv.y;
        o.z = (v[i].z - mu) * inv * gv.z + bv.z;
        o.w = (v[i].w - mu) * inv * gv.w + bv.w;
        d += o.x * o.x + o.y * o.y + o.z * o.z + o.w * o.w;
        y4[lane + 32 * i] = o;
    }
    if (diag) {
#pragma unroll
        for (int o = 16; o > 0; o >>= 1) d += __shfl_xor_sync(0xffffffffu, d, o);
        if (lane == 0) diag[w] = 0.5f * SCAL * SCAL * d;
    }
}

// ================= performer helpers =================
__global__ void lg_rowmax_kernel(float* __restrict__ lg, const float* __restrict__ diag,
                                 float* __restrict__ qmax)
{
    int row = blockIdx.x;
    int tid = threadIdx.x;
    long long idx = (long long)row * MFEAT + tid;
    float v = lg[idx] * SCAL - diag[row];
    lg[idx] = v;
    __shared__ float red[8];
    float m = v;
#pragma unroll
    for (int o = 16; o > 0; o >>= 1) m = fmaxf(m, __shfl_down_sync(0xffffffffu, m, o));
    int w = tid >> 5, lane = tid & 31;
    if (lane == 0) red[w] = m;
    __syncthreads();
    if (tid == 0) {
        float a = red[0];
        for (int i = 1; i < 8; i++) a = fmaxf(a, red[i]);
        qmax[row] = a;
    }
}

__global__ void gmax_kernel(const float* __restrict__ qmax, float* __restrict__ gmax)
{
    int tid = threadIdx.x;
    float m = -1e30f;
    for (int i = tid; i < ROWS; i += 256) m = fmaxf(m, qmax[i]);
    __shared__ float red[8];
#pragma unroll
    for (int o = 16; o > 0; o >>= 1) m = fmaxf(m, __shfl_down_sync(0xffffffffu, m, o));
    int w = tid >> 5, lane = tid & 31;
    if (lane == 0) red[w] = m;
    __syncthreads();
    if (tid == 0) {
        float a = red[0];
        for (int i = 1; i < 8; i++) a = fmaxf(a, red[i]);
        gmax[0] = a;
    }
}

__global__ void feat_kernel(const float* __restrict__ lg, const float* __restrict__ qmax,
                            const float* __restrict__ gmax,
                            float* __restrict__ qf, float* __restrict__ kfT)
{
    long long i = (long long)blockIdx.x * 256 + threadIdx.x;
    if (i >= (long long)ROWS * MFEAT) return;
    int tg = (int)(i >> 8);
    int m = (int)(i & 255);
    int b = tg / NTOK;
    int t = tg - b * NTOK;
    float v = lg[i];
    qf[i] = expf(v - qmax[tg]) * MSCL + FEPS;
    kfT[((long long)(b * MFEAT + m)) * KPAD + t] = expf(v - gmax[0]) * MSCL + FEPS;
}

__global__ void ksum_kernel(const float* __restrict__ kfT, float* __restrict__ ksum)
{
    int w = (blockIdx.x * blockDim.x + threadIdx.x) >> 5;
    int lane = threadIdx.x & 31;
    if (w >= BSZ * MFEAT) return;
    const float* p = kfT + (long long)w * KPAD;
    float s = 0.f;
#pragma unroll
    for (int t = lane; t < KPAD; t += 32) s += p[t];
#pragma unroll
    for (int o = 16; o > 0; o >>= 1) s += __shfl_down_sync(0xffffffffu, s, o);
    if (lane == 0) ksum[w] = s;
}

__global__ void den_kernel(const float* __restrict__ qf, const float* __restrict__ ksum,
                           float* __restrict__ den)
{
    int warp = (blockIdx.x * blockDim.x + threadIdx.x) >> 5;
    int lane = threadIdx.x & 31;
    if (warp >= ROWS) return;
    int b = warp / NTOK;
    const float* q  = qf + (long long)warp * MFEAT;
    const float* ks = ksum + b * MFEAT;
    float s = 0.f;
#pragma unroll
    for (int m = lane; m < MFEAT; m += 32) s += q[m] * ks[m];
#pragma unroll
    for (int o = 16; o > 0; o >>= 1) s += __shfl_down_sync(0xffffffffu, s, o);
    if (lane == 0) den[warp] = s;
}

// ================= transpose (tiled) =================
__global__ void transpose_tiled(const float* __restrict__ in, float* __restrict__ out,
                                int R, int Ccol, int ldo, long long sin, long long sout)
{
    __shared__ float t[32][33];
    const float* ip = in + (long long)blockIdx.z * sin;
    float* op = out + (long long)blockIdx.z * sout;
    int c0 = blockIdx.x * 32, r0 = blockIdx.y * 32;
    int tx = threadIdx.x, ty = threadIdx.y;
#pragma unroll
    for (int k = 0; k < 4; k++) {
        int r = r0 + ty + 8 * k;
        if (r < R && c0 + tx < Ccol)
            t[ty + 8 * k][tx] = ip[(long long)r * Ccol + c0 + tx];
    }
    __syncthreads();
#pragma unroll
    for (int k = 0; k < 4; k++) {
        int c = c0 + ty + 8 * k;
        int r = r0 + tx;
        if (c < Ccol && r < R)
            op[(long long)c * ldo + r] = t[tx][ty + 8 * k];
    }
}

// ================= misc elementwise =================
__global__ void im2col_kernel(const float* __restrict__ x, float* __restrict__ pt)
{
    long long i = (long long)blockIdx.x * 256 + threadIdx.x;
    if (i >= (long long)BSZ * NPATCH * 768) return;
    int kidx = (int)(i % 768);
    int p    = (int)(i / 768);
    int pj = kidx & 15, pi = (kidx >> 4) & 15, c = kidx >> 8;
    int gj = p % 14;
    int t  = p / 14;
    int gi = t % 14;
    int b  = t / 14;
    pt[i] = x[(((long long)(b * 3 + c) * 224 + gi * 16 + pi) * 224) + gj * 16 + pj];
}

__global__ void assemble_kernel(const float* __restrict__ tok, const float* __restrict__ cls_tok,
                                const float* __restrict__ pos, float* __restrict__ h)
{
    long long i = (long long)blockIdx.x * 256 + threadIdx.x;
    if (i >= (long long)ROWS * EDIM) return;
    int e = (int)(i % EDIM);
    int t = (int)(i / EDIM);
    int n = t % NTOK;
    int b = t / NTOK;
    float v = (n == 0) ? cls_tok[e] : tok[(long long)(b * NPATCH + n - 1) * EDIM + e];
    h[i] = v + pos[(long long)n * EDIM + e];
}

__global__ void combine_kernel(const float* __restrict__ part, const float* __restrict__ b2,
                               float* __restrict__ h)
{
    long long i = (long long)blockIdx.x * 256 + threadIdx.x;
    if (i >= (long long)ROWS * EDIM) return;
    int e = (int)(i % EDIM);
    h[i] += part[i] + part[(long long)ROWS * EDIM + i] + b2[e];
}

// ================= host =================
static inline float* sym(const void* s)
{
    void* p = nullptr;
    cudaGetSymbolAddress(&p, s);
    return (float*)p;
}

extern "C" void kernel_launch(void* const* d_in, const int* in_sizes, int n_in,
                              void* d_out, int out_size)
{
    const float* x       = (const float*)d_in[0];
    const float* cls_tok = (const float*)d_in[1];
    const float* pos_emb = (const float*)d_in[2];
    const float* patch_w = (const float*)d_in[3];
    const float* patch_b = (const float*)d_in[4];
    const float* ln1_g   = (const float*)d_in[5];
    const float* ln1_b   = (const float*)d_in[6];
    const float* proj    = (const float*)d_in[7];
    const float* ln2_g   = (const float*)d_in[8];
    const float* ln2_b   = (const float*)d_in[9];
    const float* w1      = (const float*)d_in[10];
    const float* b1      = (const float*)d_in[11];
    const float* w2      = (const float*)d_in[12];
    const float* b2      = (const float*)d_in[13];
    const float* lnf_g   = (const float*)d_in[14];
    const float* lnf_b   = (const float*)d_in[15];
    const float* head_w  = (const float*)d_in[16];
    const float* head_b  = (const float*)d_in[17];
    float* out = (float*)d_out;

    float* h    = sym(g_h);
    float* y    = sym(g_y);
    float* tmp  = sym(g_tmp);
    float* lg   = sym(g_lg);
    float* qf   = sym(g_qf);
    float* kfT  = sym(g_kfT);
    float* yT   = sym(g_yT);
    float* kvT  = sym(g_kvT);
    float* part = sym(g_part);
    float* diag = sym(g_diag);
    float* qmax = sym(g_qmax);
    float* den  = sym(g_den);
    float* ksum = sym(g_ksum);
    float* gmax = sym(g_gmax);
    float* clsb = sym(g_cls);
    float* w1T  = sym(g_w1T);
    float* w2T  = sym(g_w2T);

    float* pt  = tmp;             // [3136,768] im2col
    float* tok = tmp + 5000000;   // [3136,768] patch-embed out

    // --- weight transposes (w1T[l]: [3072,768], w2T[l]: [768,3072]) ---
    {
        dim3 blk(32, 8);
        transpose_tiled<<<dim3(96, 24, NLAYER), blk>>>(w1, w1T, EDIM, FDIM, EDIM,
            (long long)EDIM * FDIM, (long long)EDIM * FDIM);
        transpose_tiled<<<dim3(24, 96, NLAYER), blk>>>(w2, w2T, FDIM, EDIM, FDIM,
            (long long)EDIM * FDIM, (long long)EDIM * FDIM);
    }

    // --- patch embedding ---
    {
        long long tot = (long long)BSZ * NPATCH * 768;
        im2col_kernel<<<(unsigned)((tot + 255) / 256), 256>>>(x, pt);
        mma_gemm<<<dim3(6, 25, 1), 256>>>(pt, patch_w, tok,
            BSZ * NPATCH, 768, 768, EDIM, 0, 0, 0, 0, 0, 768,
            patch_b, nullptr, 0, 1);
        long long ht = (long long)ROWS * EDIM;
        assemble_kernel<<<(unsigned)((ht + 255) / 256), 256>>>(tok, cls_tok, pos_emb, h);
    }

    for (int l = 0; l < NLAYER; l++) {
        const float* prj = proj + (long long)l * MFEAT * EDIM;
        // LN1 + diag
        ln_kernel<<<(ROWS + 7) / 8, 256>>>(h, EDIM, y, EDIM,
            ln1_g + l * EDIM, ln1_b + l * EDIM, diag, ROWS);
        // logits = y @ proj^T (raw)
        mma_gemm<<<dim3(2, 25, 1), 256>>>(y, prj, lg,
            ROWS, EDIM, EDIM, MFEAT, 0, 0, 0, 0, 0, EDIM,
            nullptr, nullptr, 0, 0);
        lg_rowmax_kernel<<<ROWS, 256>>>(lg, diag, qmax);
        gmax_kernel<<<1, 256>>>(qmax, gmax);
        feat_kernel<<<(ROWS * MFEAT + 255) / 256, 256>>>(lg, qmax, gmax, qf, kfT);
        ksum_kernel<<<(BSZ * MFEAT * 32 + 255) / 256, 256>>>(kfT, ksum);
        // yT[b][e][t] (zero-padded t>=197)
        transpose_tiled<<<dim3(24, 7, BSZ), dim3(32, 8)>>>(y, yT, NTOK, EDIM, KPAD,
            (long long)NTOK * EDIM, (long long)EDIM * KPAD);
        // kvT[b] = yT[b] @ kfT[b]^T : [768,256], K=224
        mma_gemm<<<dim3(2, 6, BSZ), 256>>>(yT, kfT, kvT,
            EDIM, KPAD, KPAD, MFEAT,
            (long long)EDIM * KPAD, (long long)MFEAT * KPAD, (long long)EDIM * MFEAT,
            0, 0, KPAD, nullptr, nullptr, 0, 0);
        den_kernel<<<(ROWS + 7) / 8, 256>>>(qf, ksum, den);
        // h += (qf @ kvT^T) / den
        mma_gemm<<<dim3(6, 2, BSZ), 256>>>(qf, kvT, h,
            NTOK, MFEAT, MFEAT, EDIM,
            (long long)NTOK * MFEAT, (long long)EDIM * MFEAT, (long long)NTOK * EDIM,
            0, 0, MFEAT, nullptr, den, NTOK, 4 | 8);
        // LN2
        ln_kernel<<<(ROWS + 7) / 8, 256>>>(h, EDIM, y, EDIM,
            ln2_g + l * EDIM, ln2_b + l * EDIM, nullptr, ROWS);
        // hid = gelu(y @ w1 + b1)
        mma_gemm<<<dim3(24, 25, 1), 256>>>(y, w1T + (long long)l * EDIM * FDIM, tmp,
            ROWS, EDIM, EDIM, FDIM, 0, 0, 0, 0, 0, EDIM,
            b1 + l * FDIM, nullptr, 0, 1 | 2);
        // part[z] = hid[:, zK:] @ w2T[:, zK:]^T   (split-K over 2)
        mma_gemm<<<dim3(6, 25, 2), 256>>>(tmp, w2T + (long long)l * EDIM * FDIM, part,
            ROWS, FDIM, FDIM, EDIM, 0, 0, (long long)ROWS * EDIM,
            0, FDIM / 2, FDIM / 2, nullptr, nullptr, 0, 0);
        combine_kernel<<<(ROWS * EDIM + 255) / 256, 256>>>(part, b2 + l * EDIM, h);
    }

    // final LN on CLS tokens + head
    ln_kernel<<<2, 256>>>(h, (long long)NTOK * EDIM, clsb, EDIM, lnf_g, lnf_b, nullptr, BSZ);
    {
        dim3 grid(8, 1, 1);
        gemm_kernel<<<grid, 256>>>(clsb, head_w, out,
            BSZ, NC, EDIM, head_b, 1);
    }
}

// round 7
// speedup vs baseline: 2.4930x; 1.0445x over previous
#include <cuda_runtime.h>
#include <cuda_bf16.h>
#include <math.h>
#include <stdint.h>

// ---------------- problem constants ----------------
#define EDIM   768
#define NTOK   197
#define BSZ    16
#define ROWS   (BSZ*NTOK)      // 3152
#define MFEAT  256
#define FDIM   3072
#define NPATCH 196
#define NC     1000
#define NLAYER 12
#define KPAD   224             // 197 padded to mult of 32

#define SCAL  0.18995897f      // 768^{-1/4}
#define MSCL  0.0625f          // 256^{-1/2}
#define FEPS  1e-4f

// ---------------- scratch (device globals; allocation-free) ----------------
__device__ float g_h   [ROWS*EDIM];
__device__ float g_y   [ROWS*EDIM];
__device__ float g_tmp [ROWS*FDIM];          // MLP hidden; im2col+tok at start
__device__ float g_lg  [ROWS*MFEAT];
__device__ float g_qf  [ROWS*MFEAT];
__device__ float g_kfT [BSZ*MFEAT*KPAD];     // [b][m][t] zero-padded t>=197
__device__ float g_yT  [BSZ*EDIM*KPAD];      // [b][e][t] zero-padded
__device__ float g_kvT [BSZ*EDIM*MFEAT];     // [b][e][m]
__device__ float g_part[2*ROWS*EDIM];        // split-K partials
__device__ float g_diag[ROWS];
__device__ float g_qmax[ROWS];
__device__ float g_den [ROWS];
__device__ float g_ksum[BSZ*MFEAT];
__device__ float g_gmax[1];
__device__ float g_cls [BSZ*EDIM];
__device__ float g_w1T [NLAYER*EDIM*FDIM];   // [l][f][e]
__device__ float g_w2T [NLAYER*EDIM*FDIM];   // [l][e][f]

// ================= bf16-split mma.sync GEMM =================
// C[M, N=grid.x*128] = A[M,klen] @ B[N,klen]^T   (both fp32 K-major)
// 2-term bf16 split, 3 products: fp32-like accuracy (~1e-5).
// flags: 1=+bias[n]  2=gelu  4=accumulate into C  8=divide by rowdiv[z*sdiv+m]

#define SPITCH 40   // smem row pitch in halfs (80 bytes): conflict-free for ldmatrix

__device__ __forceinline__ void mma_bf16(float* c, const uint32_t* a, const uint32_t* b)
{
    asm volatile(
        "mma.sync.aligned.m16n8k16.row.col.f32.bf16.bf16.f32 "
        "{%0,%1,%2,%3}, {%4,%5,%6,%7}, {%8,%9}, {%0,%1,%2,%3};"
        : "+f"(c[0]), "+f"(c[1]), "+f"(c[2]), "+f"(c[3])
        : "r"(a[0]), "r"(a[1]), "r"(a[2]), "r"(a[3]), "r"(b[0]), "r"(b[1]));
}

__device__ __forceinline__ uint32_t smem_addr(const void* p)
{
    uint32_t a;
    asm("{ .reg .u64 t; cvta.to.shared.u64 t, %1; cvt.u32.u64 %0, t; }"
        : "=r"(a) : "l"(p));
    return a;
}

__device__ __forceinline__ void ldsm_x4(uint32_t* r, uint32_t addr)
{
    asm volatile("ldmatrix.sync.aligned.m8n8.x4.shared.b16 {%0,%1,%2,%3}, [%4];"
                 : "=r"(r[0]), "=r"(r[1]), "=r"(r[2]), "=r"(r[3]) : "r"(addr));
}
__device__ __forceinline__ void ldsm_x2(uint32_t* r, uint32_t addr)
{
    asm volatile("ldmatrix.sync.aligned.m8n8.x2.shared.b16 {%0,%1}, [%2];"
                 : "=r"(r[0]), "=r"(r[1]) : "r"(addr));
}

// split float4 -> packed hi(2xuint) and lo(2xuint) bf16x2
__device__ __forceinline__ void split_pack(float4 v, uint2& hi, uint2& lo)
{
    __nv_bfloat16 hx = __float2bfloat16(v.x);
    __nv_bfloat16 hy = __float2bfloat16(v.y);
    __nv_bfloat16 hz = __float2bfloat16(v.z);
    __nv_bfloat16 hw = __float2bfloat16(v.w);
    __nv_bfloat16 lx = __float2bfloat16(v.x - __bfloat162float(hx));
    __nv_bfloat16 ly = __float2bfloat16(v.y - __bfloat162float(hy));
    __nv_bfloat16 lz = __float2bfloat16(v.z - __bfloat162float(hz));
    __nv_bfloat16 lw = __float2bfloat16(v.w - __bfloat162float(hw));
    __nv_bfloat162 h0 = __halves2bfloat162(hx, hy);
    __nv_bfloat162 h1 = __halves2bfloat162(hz, hw);
    __nv_bfloat162 l0 = __halves2bfloat162(lx, ly);
    __nv_bfloat162 l1 = __halves2bfloat162(lz, lw);
    hi.x = *(uint32_t*)&h0; hi.y = *(uint32_t*)&h1;
    lo.x = *(uint32_t*)&l0; lo.y = *(uint32_t*)&l1;
}

__global__ void __launch_bounds__(256) mma_gemm(
    const float* __restrict__ A, const float* __restrict__ B, float* __restrict__ C,
    int M, int ldA, int ldB, int ldC,
    long long sA, long long sB, long long sC,
    int kstart, int kzs, int klen,
    const float* __restrict__ bias, const float* __restrict__ rowdiv, int sdiv, int flags)
{
    __shared__ __align__(16) __nv_bfloat16 Ah[128 * SPITCH];
    __shared__ __align__(16) __nv_bfloat16 Al[128 * SPITCH];
    __shared__ __align__(16) __nv_bfloat16 Bh[128 * SPITCH];
    __shared__ __align__(16) __nv_bfloat16 Bl[128 * SPITCH];

    int tid = threadIdx.x;
    int wid = tid >> 5, lane = tid & 31;
    int m0 = blockIdx.y * 128, n0 = blockIdx.x * 128, z = blockIdx.z;
    int warpM = wid >> 2;          // 0..1 -> 64 rows
    int warpN = wid & 3;           // 0..3 -> 32 cols
    int qr = lane >> 2;            // group row 0..7
    int qc = (lane & 3) * 2;       // k pair base

    // ldmatrix per-lane byte offsets
    uint32_t AhB = smem_addr(Ah), AlB = smem_addr(Al);
    uint32_t BhB = smem_addr(Bh), BlB = smem_addr(Bl);
    uint32_t aoff = (uint32_t)(((warpM * 64 + (lane & 15)) * SPITCH + ((lane >> 4) << 3)) * 2);
    uint32_t boff = (uint32_t)(((warpN * 32 + (lane & 7)) * SPITCH + (((lane >> 3) & 1) << 3)) * 2);

    const float* Ab = A + (long long)z * sA + kstart + (long long)z * kzs;
    const float* Bb = B + (long long)z * sB + kstart + (long long)z * kzs;

    float acc[4][4][4];
#pragma unroll
    for (int i = 0; i < 4; i++)
#pragma unroll
        for (int j = 0; j < 4; j++)
#pragma unroll
            for (int r = 0; r < 4; r++) acc[i][j][r] = 0.f;

    int kt_n = klen >> 5;

    // prefetch tile 0 into regs
    float4 av[4], bv[4];
#pragma unroll
    for (int i = 0; i < 4; i++) {
        int idx = tid + (i << 8);
        int r = idx >> 3, c4 = idx & 7;
        int gm = m0 + r;
        av[i] = (gm < M) ? *(const float4*)(Ab + (long long)gm * ldA + (c4 << 2))
                         : make_float4(0.f, 0.f, 0.f, 0.f);
        bv[i] = *(const float4*)(Bb + (long long)(n0 + r) * ldB + (c4 << 2));
    }

    for (int kt = 0; kt < kt_n; kt++) {
        __syncthreads();   // previous compute done; smem reusable
        // convert + store current tile
#pragma unroll
        for (int i = 0; i < 4; i++) {
            int idx = tid + (i << 8);
            int r = idx >> 3, c4 = idx & 7;
            int ho = r * SPITCH + c4 * 4;
            uint2 hi, lo;
            split_pack(av[i], hi, lo);
            *(uint2*)&Ah[ho] = hi; *(uint2*)&Al[ho] = lo;
            split_pack(bv[i], hi, lo);
            *(uint2*)&Bh[ho] = hi; *(uint2*)&Bl[ho] = lo;
        }
        __syncthreads();
        // prefetch next tile
        if (kt + 1 < kt_n) {
            long long ko = ((long long)(kt + 1) << 5);
#pragma unroll
            for (int i = 0; i < 4; i++) {
                int idx = tid + (i << 8);
                int r = idx >> 3, c4 = idx & 7;
                int gm = m0 + r;
                av[i] = (gm < M) ? *(const float4*)(Ab + (long long)gm * ldA + ko + (c4 << 2))
                                 : make_float4(0.f, 0.f, 0.f, 0.f);
                bv[i] = *(const float4*)(Bb + (long long)(n0 + r) * ldB + ko + (c4 << 2));
            }
        }
        // compute 32-deep K slab
#pragma unroll
        for (int ks = 0; ks < 2; ks++) {
            uint32_t kbyte = (uint32_t)(ks * 16 * 2);
            uint32_t bhf[4][2], blf[4][2];
#pragma unroll
            for (int nt = 0; nt < 4; nt++) {
                uint32_t bo = boff + (uint32_t)(nt * 8 * SPITCH * 2) + kbyte;
                ldsm_x2(bhf[nt], BhB + bo);
                ldsm_x2(blf[nt], BlB + bo);
            }
#pragma unroll
            for (int mt = 0; mt < 4; mt++) {
                uint32_t ao = aoff + (uint32_t)(mt * 16 * SPITCH * 2) + kbyte;
                uint32_t ahf[4], alf[4];
                ldsm_x4(ahf, AhB + ao);
                ldsm_x4(alf, AlB + ao);
#pragma unroll
                for (int nt = 0; nt < 4; nt++) {
                    mma_bf16(acc[mt][nt], ahf, bhf[nt]);
                    mma_bf16(acc[mt][nt], ahf, blf[nt]);
                    mma_bf16(acc[mt][nt], alf, bhf[nt]);
                }
            }
        }
    }

    // ---- epilogue ----
#pragma unroll
    for (int mt = 0; mt < 4; mt++) {
        int r0 = m0 + warpM * 64 + mt * 16 + qr;
        int r1 = r0 + 8;
        bool ok0 = r0 < M, ok1 = r1 < M;
        float dv0 = 1.f, dv1 = 1.f;
        if (flags & 8) {
            if (ok0) dv0 = 1.f / rowdiv[(long long)z * sdiv + r0];
            if (ok1) dv1 = 1.f / rowdiv[(long long)z * sdiv + r1];
        }
        float* row0 = C + (long long)z * sC + (long long)r0 * ldC;
        float* row1 = C + (long long)z * sC + (long long)r1 * ldC;
#pragma unroll
        for (int nt = 0; nt < 4; nt++) {
            int col = n0 + warpN * 32 + nt * 8 + qc;
            float b0 = 0.f, b1 = 0.f;
            if (flags & 1) { b0 = bias[col]; b1 = bias[col + 1]; }
#pragma unroll
            for (int half = 0; half < 2; half++) {
                bool ok = half ? ok1 : ok0;
                if (!ok) continue;
                float dv = half ? dv1 : dv0;
                float* row = half ? row1 : row0;
                float v0 = acc[mt][nt][half * 2 + 0];
                float v1 = acc[mt][nt][half * 2 + 1];
                v0 += b0; v1 += b1;
                if (flags & 2) {
                    v0 = 0.5f * v0 * (1.f + erff(v0 * 0.70710678118654752f));
                    v1 = 0.5f * v1 * (1.f + erff(v1 * 0.70710678118654752f));
                }
                if (flags & 8) { v0 *= dv; v1 *= dv; }
                if (flags & 4) { v0 += row[col]; v1 += row[col + 1]; }
                row[col] = v0; row[col + 1] = v1;
            }
        }
    }
}

// ================= fallback SGEMM (head only) =================
__global__ void __launch_bounds__(256) gemm_kernel(
    const float* __restrict__ A, const float* __restrict__ B, float* __restrict__ C,
    int M, int N, int K,
    const float* __restrict__ bias, int flags)
{
    __shared__ __align__(16) float As[8][128];
    __shared__ __align__(16) float Bs[8][128];
    int tid = threadIdx.x;
    int m0 = blockIdx.y * 128;
    int n0 = blockIdx.x * 128;
    int tx = tid & 15, ty = tid >> 4;
    float acc[8][8];
#pragma unroll
    for (int i = 0; i < 8; i++)
#pragma unroll
        for (int j = 0; j < 8; j++) acc[i][j] = 0.f;
    for (int k0 = 0; k0 < K; k0 += 8) {
#pragma unroll
        for (int i = 0; i < 4; i++) {
            int l = tid + i * 256;
            int mm = l >> 3, kk = l & 7;
            int gk = k0 + kk, gm = m0 + mm;
            As[kk][mm] = (gk < K && gm < M) ? A[(long long)gm * K + gk] : 0.f;
        }
#pragma unroll
        for (int i = 0; i < 4; i++) {
            int l = tid + i * 256;
            int kk = l >> 7, nn = l & 127;
            int gk = k0 + kk, gn = n0 + nn;
            Bs[kk][nn] = (gk < K && gn < N) ? B[(long long)gk * N + gn] : 0.f;
        }
        __syncthreads();
#pragma unroll
        for (int k = 0; k < 8; k++) {
            float4 a0 = *(const float4*)&As[k][ty * 4];
            float4 a1 = *(const float4*)&As[k][ty * 4 + 64];
            float4 b0 = *(const float4*)&Bs[k][tx * 4];
            float4 b1 = *(const float4*)&Bs[k][tx * 4 + 64];
            float af[8] = {a0.x, a0.y, a0.z, a0.w, a1.x, a1.y, a1.z, a1.w};
            float bf[8] = {b0.x, b0.y, b0.z, b0.w, b1.x, b1.y, b1.z, b1.w};
#pragma unroll
            for (int i = 0; i < 8; i++)
#pragma unroll
                for (int j = 0; j < 8; j++) acc[i][j] += af[i] * bf[j];
        }
        __syncthreads();
    }
#pragma unroll
    for (int i = 0; i < 8; i++) {
        int gm = m0 + ((i < 4) ? ty * 4 + i : 64 + ty * 4 + (i - 4));
        if (gm >= M) continue;
        float* crow = C + (long long)gm * N;
#pragma unroll
        for (int j = 0; j < 8; j++) {
            int gn = n0 + ((j < 4) ? tx * 4 + j : 64 + tx * 4 + (j - 4));
            if (gn >= N) continue;
            float v = acc[i][j];
            if (flags & 1) v += bias[gn];
            crow[gn] = v;
        }
    }
}

// ================= layernorm: warp per row =================
__global__ void ln_kernel(const float* __restrict__ X, long long ldx,
                          float* __restrict__ Y, long long ldy,
                          const float* __restrict__ g, const float* __restrict__ b,
                          float* __restrict__ diag, int nrows)
{
    int w = blockIdx.x * (blockDim.x >> 5) + (threadIdx.x >> 5);
    int lane = threadIdx.x & 31;
    if (w >= nrows) return;
    const float4* x = (const float4*)(X + (long long)w * ldx);
    float4 v[6];
    float s1 = 0.f, s2 = 0.f;
#pragma unroll
    for (int i = 0; i < 6; i++) {
        v[i] = x[lane + 32 * i];
        s1 += v[i].x + v[i].y + v[i].z + v[i].w;
        s2 += v[i].x * v[i].x + v[i].y * v[i].y + v[i].z * v[i].z + v[i].w * v[i].w;
    }
#pragma unroll
    for (int o = 16; o > 0; o >>= 1) {
        s1 += __shfl_xor_sync(0xffffffffu, s1, o);
        s2 += __shfl_xor_sync(0xffffffffu, s2, o);
    }
    float mu  = s1 * (1.0f / 768.0f);
    float var = s2 * (1.0f / 768.0f) - mu * mu;
    float inv = rsqrtf(var + 1e-5f);
    const float4* g4 = (const float4*)g;
    const float4* b4 = (const float4*)b;
    float4* y4 = (float4*)(Y + (long long)w * ldy);
    float d = 0.f;
#pragma unroll
    for (int i = 0; i < 6; i++) {
        float4 gv = g4[lane + 32 * i], bv = b4[lane + 32 * i], o;
        o.x = (v[i].x - mu) * inv * gv.x + bv.x;
        o.y = (v[i].y - mu) * inv * gv.y + bv.y;
        o.z = (v[i].z - mu) * inv * gv.z + bv.z;
        o.w = (v[i].w - mu) * inv * gv.w + bv.w;
        d += o.x * o.x + o.y * o.y + o.z * o.z + o.w * o.w;
        y4[lane + 32 * i] = o;
    }
    if (diag) {
#pragma unroll
        for (int o = 16; o > 0; o >>= 1) d += __shfl_xor_sync(0xffffffffu, d, o);
        if (lane == 0) diag[w] = 0.5f * SCAL * SCAL * d;
    }
}

// ================= performer helpers =================
__global__ void lg_rowmax_kernel(float* __restrict__ lg, const float* __restrict__ diag,
                                 float* __restrict__ qmax)
{
    int row = blockIdx.x;
    int tid = threadIdx.x;
    long long idx = (long long)row * MFEAT + tid;
    float v = lg[idx] * SCAL - diag[row];
    lg[idx] = v;
    __shared__ float red[8];
    float m = v;
#pragma unroll
    for (int o = 16; o > 0; o >>= 1) m = fmaxf(m, __shfl_down_sync(0xffffffffu, m, o));
    int w = tid >> 5, lane = tid & 31;
    if (lane == 0) red[w] = m;
    __syncthreads();
    if (tid == 0) {
        float a = red[0];
        for (int i = 1; i < 8; i++) a = fmaxf(a, red[i]);
        qmax[row] = a;
    }
}

__global__ void gmax_kernel(const float* __restrict__ qmax, float* __restrict__ gmax)
{
    int tid = threadIdx.x;
    float m = -1e30f;
    for (int i = tid; i < ROWS; i += 256) m = fmaxf(m, qmax[i]);
    __shared__ float red[8];
#pragma unroll
    for (int o = 16; o > 0; o >>= 1) m = fmaxf(m, __shfl_down_sync(0xffffffffu, m, o));
    int w = tid >> 5, lane = tid & 31;
    if (lane == 0) red[w] = m;
    __syncthreads();
    if (tid == 0) {
        float a = red[0];
        for (int i = 1; i < 8; i++) a = fmaxf(a, red[i]);
        gmax[0] = a;
    }
}

__global__ void feat_kernel(const float* __restrict__ lg, const float* __restrict__ qmax,
                            const float* __restrict__ gmax,
                            float* __restrict__ qf, float* __restrict__ kfT)
{
    long long i = (long long)blockIdx.x * 256 + threadIdx.x;
    if (i >= (long long)ROWS * MFEAT) return;
    int tg = (int)(i >> 8);
    int m = (int)(i & 255);
    int b = tg / NTOK;
    int t = tg - b * NTOK;
    float v = lg[i];
    qf[i] = expf(v - qmax[tg]) * MSCL + FEPS;
    kfT[((long long)(b * MFEAT + m)) * KPAD + t] = expf(v - gmax[0]) * MSCL + FEPS;
}

__global__ void ksum_kernel(const float* __restrict__ kfT, float* __restrict__ ksum)
{
    int w = (blockIdx.x * blockDim.x + threadIdx.x) >> 5;
    int lane = threadIdx.x & 31;
    if (w >= BSZ * MFEAT) return;
    const float* p = kfT + (long long)w * KPAD;
    float s = 0.f;
#pragma unroll
    for (int t = lane; t < KPAD; t += 32) s += p[t];
#pragma unroll
    for (int o = 16; o > 0; o >>= 1) s += __shfl_down_sync(0xffffffffu, s, o);
    if (lane == 0) ksum[w] = s;
}

__global__ void den_kernel(const float* __restrict__ qf, const float* __restrict__ ksum,
                           float* __restrict__ den)
{
    int warp = (blockIdx.x * blockDim.x + threadIdx.x) >> 5;
    int lane = threadIdx.x & 31;
    if (warp >= ROWS) return;
    int b = warp / NTOK;
    const float* q  = qf + (long long)warp * MFEAT;
    const float* ks = ksum + b * MFEAT;
    float s = 0.f;
#pragma unroll
    for (int m = lane; m < MFEAT; m += 32) s += q[m] * ks[m];
#pragma unroll
    for (int o = 16; o > 0; o >>= 1) s += __shfl_down_sync(0xffffffffu, s, o);
    if (lane == 0) den[warp] = s;
}

// ================= transpose (tiled) =================
__global__ void transpose_tiled(const float* __restrict__ in, float* __restrict__ out,
                                int R, int Ccol, int ldo, long long sin, long long sout)
{
    __shared__ float t[32][33];
    const float* ip = in + (long long)blockIdx.z * sin;
    float* op = out + (long long)blockIdx.z * sout;
    int c0 = blockIdx.x * 32, r0 = blockIdx.y * 32;
    int tx = threadIdx.x, ty = threadIdx.y;
#pragma unroll
    for (int k = 0; k < 4; k++) {
        int r = r0 + ty + 8 * k;
        if (r < R && c0 + tx < Ccol)
            t[ty + 8 * k][tx] = ip[(long long)r * Ccol + c0 + tx];
    }
    __syncthreads();
#pragma unroll
    for (int k = 0; k < 4; k++) {
        int c = c0 + ty + 8 * k;
        int r = r0 + tx;
        if (c < Ccol && r < R)
            op[(long long)c * ldo + r] = t[tx][ty + 8 * k];
    }
}

// ================= misc elementwise =================
__global__ void im2col_kernel(const float* __restrict__ x, float* __restrict__ pt)
{
    long long i = (long long)blockIdx.x * 256 + threadIdx.x;
    if (i >= (long long)BSZ * NPATCH * 768) return;
    int kidx = (int)(i % 768);
    int p    = (int)(i / 768);
    int pj = kidx & 15, pi = (kidx >> 4) & 15, c = kidx >> 8;
    int gj = p % 14;
    int t  = p / 14;
    int gi = t % 14;
    int b  = t / 14;
    pt[i] = x[(((long long)(b * 3 + c) * 224 + gi * 16 + pi) * 224) + gj * 16 + pj];
}

__global__ void assemble_kernel(const float* __restrict__ tok, const float* __restrict__ cls_tok,
                                const float* __restrict__ pos, float* __restrict__ h)
{
    long long i = (long long)blockIdx.x * 256 + threadIdx.x;
    if (i >= (long long)ROWS * EDIM) return;
    int e = (int)(i % EDIM);
    int t = (int)(i / EDIM);
    int n = t % NTOK;
    int b = t / NTOK;
    float v = (n == 0) ? cls_tok[e] : tok[(long long)(b * NPATCH + n - 1) * EDIM + e];
    h[i] = v + pos[(long long)n * EDIM + e];
}

__global__ void combine_kernel(const float* __restrict__ part, const float* __restrict__ b2,
                               float* __restrict__ h)
{
    long long i = (long long)blockIdx.x * 256 + threadIdx.x;
    if (i >= (long long)ROWS * EDIM) return;
    int e = (int)(i % EDIM);
    h[i] += part[i] + part[(long long)ROWS * EDIM + i] + b2[e];
}

// ================= host =================
static inline float* sym(const void* s)
{
    void* p = nullptr;
    cudaGetSymbolAddress(&p, s);
    return (float*)p;
}

extern "C" void kernel_launch(void* const* d_in, const int* in_sizes, int n_in,
                              void* d_out, int out_size)
{
    const float* x       = (const float*)d_in[0];
    const float* cls_tok = (const float*)d_in[1];
    const float* pos_emb = (const float*)d_in[2];
    const float* patch_w = (const float*)d_in[3];
    const float* patch_b = (const float*)d_in[4];
    const float* ln1_g   = (const float*)d_in[5];
    const float* ln1_b   = (const float*)d_in[6];
    const float* proj    = (const float*)d_in[7];
    const float* ln2_g   = (const float*)d_in[8];
    const float* ln2_b   = (const float*)d_in[9];
    const float* w1      = (const float*)d_in[10];
    const float* b1      = (const float*)d_in[11];
    const float* w2      = (const float*)d_in[12];
    const float* b2      = (const float*)d_in[13];
    const float* lnf_g   = (const float*)d_in[14];
    const float* lnf_b   = (const float*)d_in[15];
    const float* head_w  = (const float*)d_in[16];
    const float* head_b  = (const float*)d_in[17];
    float* out = (float*)d_out;

    float* h    = sym(g_h);
    float* y    = sym(g_y);
    float* tmp  = sym(g_tmp);
    float* lg   = sym(g_lg);
    float* qf   = sym(g_qf);
    float* kfT  = sym(g_kfT);
    float* yT   = sym(g_yT);
    float* kvT  = sym(g_kvT);
    float* part = sym(g_part);
    float* diag = sym(g_diag);
    float* qmax = sym(g_qmax);
    float* den  = sym(g_den);
    float* ksum = sym(g_ksum);
    float* gmax = sym(g_gmax);
    float* clsb = sym(g_cls);
    float* w1T  = sym(g_w1T);
    float* w2T  = sym(g_w2T);

    float* pt  = tmp;             // [3136,768] im2col
    float* tok = tmp + 5000000;   // [3136,768] patch-embed out

    // --- weight transposes (w1T[l]: [3072,768], w2T[l]: [768,3072]) ---
    {
        dim3 blk(32, 8);
        transpose_tiled<<<dim3(96, 24, NLAYER), blk>>>(w1, w1T, EDIM, FDIM, EDIM,
            (long long)EDIM * FDIM, (long long)EDIM * FDIM);
        transpose_tiled<<<dim3(24, 96, NLAYER), blk>>>(w2, w2T, FDIM, EDIM, FDIM,
            (long long)EDIM * FDIM, (long long)EDIM * FDIM);
    }

    // --- patch embedding ---
    {
        long long tot = (long long)BSZ * NPATCH * 768;
        im2col_kernel<<<(unsigned)((tot + 255) / 256), 256>>>(x, pt);
        mma_gemm<<<dim3(6, 25, 1), 256>>>(pt, patch_w, tok,
            BSZ * NPATCH, 768, 768, EDIM, 0, 0, 0, 0, 0, 768,
            patch_b, nullptr, 0, 1);
        long long ht = (long long)ROWS * EDIM;
        assemble_kernel<<<(unsigned)((ht + 255) / 256), 256>>>(tok, cls_tok, pos_emb, h);
    }

    for (int l = 0; l < NLAYER; l++) {
        const float* prj = proj + (long long)l * MFEAT * EDIM;
        // LN1 + diag
        ln_kernel<<<(ROWS + 7) / 8, 256>>>(h, EDIM, y, EDIM,
            ln1_g + l * EDIM, ln1_b + l * EDIM, diag, ROWS);
        // logits = y @ proj^T (raw)
        mma_gemm<<<dim3(2, 25, 1), 256>>>(y, prj, lg,
            ROWS, EDIM, EDIM, MFEAT, 0, 0, 0, 0, 0, EDIM,
            nullptr, nullptr, 0, 0);
        lg_rowmax_kernel<<<ROWS, 256>>>(lg, diag, qmax);
        gmax_kernel<<<1, 256>>>(qmax, gmax);
        feat_kernel<<<(ROWS * MFEAT + 255) / 256, 256>>>(lg, qmax, gmax, qf, kfT);
        ksum_kernel<<<(BSZ * MFEAT * 32 + 255) / 256, 256>>>(kfT, ksum);
        // yT[b][e][t] (zero-padded t>=197)
        transpose_tiled<<<dim3(24, 7, BSZ), dim3(32, 8)>>>(y, yT, NTOK, EDIM, KPAD,
            (long long)NTOK * EDIM, (long long)EDIM * KPAD);
        // kvT[b] = yT[b] @ kfT[b]^T : [768,256], K=224
        mma_gemm<<<dim3(2, 6, BSZ), 256>>>(yT, kfT, kvT,
            EDIM, KPAD, KPAD, MFEAT,
            (long long)EDIM * KPAD, (long long)MFEAT * KPAD, (long long)EDIM * MFEAT,
            0, 0, KPAD, nullptr, nullptr, 0, 0);
        den_kernel<<<(ROWS + 7) / 8, 256>>>(qf, ksum, den);
        // h += (qf @ kvT^T) / den
        mma_gemm<<<dim3(6, 2, BSZ), 256>>>(qf, kvT, h,
            NTOK, MFEAT, MFEAT, EDIM,
            (long long)NTOK * MFEAT, (long long)EDIM * MFEAT, (long long)NTOK * EDIM,
            0, 0, MFEAT, nullptr, den, NTOK, 4 | 8);
        // LN2
        ln_kernel<<<(ROWS + 7) / 8, 256>>>(h, EDIM, y, EDIM,
            ln2_g + l * EDIM, ln2_b + l * EDIM, nullptr, ROWS);
        // hid = gelu(y @ w1 + b1)
        mma_gemm<<<dim3(24, 25, 1), 256>>>(y, w1T + (long long)l * EDIM * FDIM, tmp,
            ROWS, EDIM, EDIM, FDIM, 0, 0, 0, 0, 0, EDIM,
            b1 + l * FDIM, nullptr, 0, 1 | 2);
        // part[z] = hid[:, zK:] @ w2T[:, zK:]^T   (split-K over 2)
        mma_gemm<<<dim3(6, 25, 2), 256>>>(tmp, w2T + (long long)l * EDIM * FDIM, part,
            ROWS, FDIM, FDIM, EDIM, 0, 0, (long long)ROWS * EDIM,
            0, FDIM / 2, FDIM / 2, nullptr, nullptr, 0, 0);
        combine_kernel<<<(ROWS * EDIM + 255) / 256, 256>>>(part, b2 + l * EDIM, h);
    }

    // final LN on CLS tokens + head
    ln_kernel<<<2, 256>>>(h, (long long)NTOK * EDIM, clsb, EDIM, lnf_g, lnf_b, nullptr, BSZ);
    {
        dim3 grid(8, 1, 1);
        gemm_kernel<<<grid, 256>>>(clsb, head_w, out,
            BSZ, NC, EDIM, head_b, 1);
    }
}